// round 13
// baseline (speedup 1.0000x reference)
#include <cuda_runtime.h>
#include <cuda_bf16.h>
#include <cstdint>

// ---------------------------------------------------------------------------
// VectorQuantizerEMA on GB300 (sm_103a) — R13
// R12 HMMA screening with 512 threads / 16 warps (4 per SMSP): warp grid
// 4(wm) x 4(wn), 32 codes per warp column. Discriminates latency-bound vs
// HMMA-fallback-throughput-bound. Math identical to R11/R12.
// ---------------------------------------------------------------------------

namespace {
constexpr int Dm   = 64;
constexpr int Tm   = 4096;
constexpr int Bm   = 32;
constexpr int Km   = 1024;
constexpr int Nm   = Bm * Tm;      // 131072
constexpr int MPTS = 128;          // points per block
constexpr int NCH  = 128;          // codes per chunk
constexpr int NCHUNK = Km / NCH;   // 8
constexpr int KAUG = 208;
constexpr int KSTEPS = KAUG / 16;  // 13
constexpr int ROWB = KAUG + 8;     // 216 bf16 = 432B row stride
constexpr int NT   = 512;          // threads
constexpr float DECAY = 0.99f;
constexpr float EPSm  = 1e-5f;
constexpr float MARGIN_D = 7.5e-3f;

constexpr size_t OFF_ZQ   = 0;
constexpr size_t SZ_ZQ    = (size_t)Bm * Dm * Tm;
constexpr size_t OFF_LOSS = SZ_ZQ;
constexpr size_t OFF_IDX  = SZ_ZQ + 1;
constexpr size_t SZ_FULL  = SZ_ZQ + 1 + (size_t)Nm;

// dynamic smem layout (bytes)
constexpr int S_FLAG = 0;         // 128*4
constexpr int S_FIDX = 512;       // 128*4
constexpr int S_RB   = 1024;      // 512*8 = 4096
constexpr int S_RI   = 5120;      // 512*4 = 2048
constexpr int S_BM   = 7168;      // 4*128*4 = 2048
constexpr int S_B2M  = 9216;      // 2048
constexpr int S_IM   = 11264;     // 2048
constexpr int S_Z32  = 13312;     // 128*65*4 = 33280
constexpr int S_A    = 46592;     // 128*432 = 55296 (128B aligned)
constexpr int S_B0   = 101888;    // 55296
constexpr int S_B1   = 157184;    // 55296
constexpr int SMEM_SZ= 212480;    // < 227KB cap
}

// ----------------- device scratch ------------------------------------------
__device__ float g_counts[Km];
__device__ __align__(16) float g_embed_sum[Km * Dm];
__device__ float g_smoothed[Km];
__device__ __align__(16) float g_new_embedding[Km * Dm];
__device__ int   g_indices[Nm];
__device__ float g_loss;
__device__ __align__(16) __nv_bfloat16 g_beq[Km * ROWB];   // augmented B rows

// ----------------- helpers --------------------------------------------------
__device__ __forceinline__ uint32_t smem_u32(const void* p) {
    uint32_t a;
    asm("{ .reg .u64 t; cvta.to.shared.u64 t, %1; cvt.u32.u64 %0, t; }"
        : "=r"(a) : "l"(p));
    return a;
}
__device__ __forceinline__ void red_add_v4(float* p, float a, float b, float c, float d) {
    asm volatile("red.global.add.v4.f32 [%0], {%1, %2, %3, %4};"
                 :: "l"(p), "f"(a), "f"(b), "f"(c), "f"(d) : "memory");
}
__device__ __forceinline__ void ldsm_x4(uint32_t& r0, uint32_t& r1,
                                        uint32_t& r2, uint32_t& r3, uint32_t addr) {
    asm volatile("ldmatrix.sync.aligned.m8n8.x4.shared.b16 {%0,%1,%2,%3}, [%4];"
                 : "=r"(r0), "=r"(r1), "=r"(r2), "=r"(r3) : "r"(addr));
}
__device__ __forceinline__ void mma16816(float* d, const uint32_t* a,
                                         const uint32_t* b) {
    asm volatile(
        "mma.sync.aligned.m16n8k16.row.col.f32.bf16.bf16.f32 "
        "{%0,%1,%2,%3}, {%4,%5,%6,%7}, {%8,%9}, {%0,%1,%2,%3};"
        : "+f"(d[0]), "+f"(d[1]), "+f"(d[2]), "+f"(d[3])
        : "r"(a[0]), "r"(a[1]), "r"(a[2]), "r"(a[3]), "r"(b[0]), "r"(b[1]));
}
__device__ __forceinline__ void cp_async16(uint32_t saddr, const void* gptr) {
    asm volatile("cp.async.cg.shared.global [%0], [%1], 16;"
                 :: "r"(saddr), "l"(gptr) : "memory");
}
#define CP_COMMIT() asm volatile("cp.async.commit_group;" ::: "memory")
#define CP_WAIT0()  asm volatile("cp.async.wait_group 0;" ::: "memory")

// ----------------- init kernels ----------------------------------------------
__global__ void k_zero1() {
    int i = blockIdx.x * blockDim.x + threadIdx.x;
    g_embed_sum[i] = 0.0f;
}
__global__ void k_zero2() {
    int i = blockIdx.x * blockDim.x + threadIdx.x;
    if (i < Km * Dm / 2) g_embed_sum[Km * Dm / 2 + i] = 0.0f;
    else if (i < Km * Dm / 2 + Km) g_counts[i - Km * Dm / 2] = 0.0f;
    else if (i == Km * Dm / 2 + Km) g_loss = 0.0f;
}
// build augmented B rows: [ehi|ehi|elo| -c2/2 hi,lo,ll | zeros]
__global__ void k_prep(const float* __restrict__ emb) {
    int k = blockIdx.x * blockDim.x + threadIdx.x;     // 1024
    const float* row = emb + (size_t)k * Dm;
    __nv_bfloat16* dst = g_beq + (size_t)k * ROWB;
    double s = 0.0;
#pragma unroll
    for (int d = 0; d < Dm; ++d) {
        float f = row[d];
        s += (double)f * f;
        __nv_bfloat16 hi = __float2bfloat16_rn(f);
        float rem = f - __bfloat162float(hi);
        __nv_bfloat16 lo = __float2bfloat16_rn(rem);
        dst[d] = hi;
        dst[64 + d] = hi;
        dst[128 + d] = lo;
    }
    double c = -0.5 * s;
    float c1 = (float)c;
    __nv_bfloat16 h0 = __float2bfloat16_rn(c1);
    float r1 = (float)(c - (double)__bfloat162float(h0));
    __nv_bfloat16 h1 = __float2bfloat16_rn(r1);
    float r2 = r1 - __bfloat162float(h1);
    __nv_bfloat16 h2 = __float2bfloat16_rn(r2);
    dst[192] = h0; dst[193] = h1; dst[194] = h2;
#pragma unroll
    for (int j = 195; j < ROWB; ++j) dst[j] = __float2bfloat16_rn(0.0f);
}

// ----------------- k_argmin: 16-warp HMMA screening + fp64 rescue ------------
__global__ void __launch_bounds__(NT, 1)
k_argmin(const float* __restrict__ z, const float* __restrict__ emb,
         float* __restrict__ idx_out) {
    extern __shared__ char smem[];
    const uint32_t sbase = smem_u32(smem);
    float*  z32    = reinterpret_cast<float*>(smem + S_Z32);     // [128][65]
    int*    s_flag = reinterpret_cast<int*>(smem + S_FLAG);
    int*    s_fidx = reinterpret_cast<int*>(smem + S_FIDX);
    double* s_rb   = reinterpret_cast<double*>(smem + S_RB);
    int*    s_ri   = reinterpret_cast<int*>(smem + S_RI);
    float*  s_bm   = reinterpret_cast<float*>(smem + S_BM);      // [4][128]
    float*  s_b2m  = reinterpret_cast<float*>(smem + S_B2M);
    int*    s_im   = reinterpret_cast<int*>(smem + S_IM);

    const int tid  = threadIdx.x;
    const int wid  = tid >> 5;
    const int lane = tid & 31;
    const int wm   = wid >> 2;        // 0..3 : point rows wm*32..
    const int wn   = wid & 3;         // 0..3 : code cols wn*32..
    const int n0   = blockIdx.x * MPTS;
    const int b    = n0 >> 12;
    const int t0   = n0 & (Tm - 1);
    const float* zb = z + ((size_t)b * Dm) * Tm + t0;
    const uint4* beq4 = reinterpret_cast<const uint4*>(g_beq);

    // ---- async copy of B chunk 0 (overlaps z load + A build) ----
    for (int m = tid; m < 128 * 27; m += NT) {
        int row = m / 27, u = m - row * 27;
        cp_async16(sbase + S_B0 + row * 432 + u * 16,
                   &beq4[(size_t)row * 27 + u]);
    }
    CP_COMMIT();

    // ---- load z tile (coalesced along t) ----
#pragma unroll
    for (int q = 0; q < 16; ++q) {
        int m = tid + q * NT;
        int d = m >> 7, t = m & 127;
        z32[t * 65 + d] = zb[(size_t)d * Tm + t];
    }
    __syncthreads();

    // ---- build augmented A rows (bf16, stride 216) ----
    {
        int pt = tid & 127, qd = tid >> 7;            // qd: 16-dim quarter
        __nv_bfloat16* arow = reinterpret_cast<__nv_bfloat16*>(smem + S_A) +
                              (size_t)pt * ROWB;
#pragma unroll
        for (int dd = 0; dd < 16; ++dd) {
            int d = qd * 16 + dd;
            float f = z32[pt * 65 + d];
            __nv_bfloat16 hi = __float2bfloat16_rn(f);
            __nv_bfloat16 lo = __float2bfloat16_rn(f - __bfloat162float(hi));
            arow[d] = hi;
            arow[64 + d] = lo;
            arow[128 + d] = hi;
        }
        if (qd == 3) {
            const __nv_bfloat16 one  = __float2bfloat16_rn(1.0f);
            const __nv_bfloat16 zero = __float2bfloat16_rn(0.0f);
#pragma unroll
            for (int j = 192; j < ROWB; ++j) arow[j] = (j < 195) ? one : zero;
        }
    }

    // ---- per-lane ldmatrix base addresses ----
    const int sel = lane >> 3, l8 = lane & 7;
    const uint32_t aBase = sbase + S_A +
        (uint32_t)((wm * 32 + l8 + (sel & 1) * 8) * 432 + ((sel >> 1) & 1) * 16);
    const uint32_t bOff =
        (uint32_t)((wn * 32 + l8 + ((sel >> 1) & 1) * 8) * 432 + (sel & 1) * 16);
    const uint32_t bBasePing = sbase + S_B0 + bOff;
    const uint32_t bBasePong = sbase + S_B1 + bOff;

    float dacc[2][4][4];
    float bestv[4], best2v[4];
    int   bidx[4];
#pragma unroll
    for (int s = 0; s < 4; ++s) { bestv[s] = -3.4e38f; best2v[s] = -3.4e38f; bidx[s] = 0; }

    CP_WAIT0();
    __syncthreads();                       // B chunk 0 resident

    for (int ch = 0; ch < NCHUNK; ++ch) {
        const int cb = ch * NCH;
        const uint32_t bBase = (ch & 1) ? bBasePong : bBasePing;

        // prefetch next chunk into the other buffer
        if (ch + 1 < NCHUNK) {
            const uint32_t dstB = sbase + ((ch & 1) ? S_B0 : S_B1);
            for (int m = tid; m < 128 * 27; m += NT) {
                int row = m / 27, u = m - row * 27;
                cp_async16(dstB + row * 432 + u * 16,
                           &beq4[(size_t)((ch + 1) * NCH + row) * 27 + u]);
            }
            CP_COMMIT();
        }

#pragma unroll
        for (int mt = 0; mt < 2; ++mt)
#pragma unroll
            for (int nt = 0; nt < 4; ++nt)
#pragma unroll
                for (int c = 0; c < 4; ++c) dacc[mt][nt][c] = 0.0f;

        // ---- software-pipelined kstep loop (double-buffered frags) ----
        uint32_t afr[2][8], bfr[2][8];
        {   // prologue: frags for ks=0
            ldsm_x4(afr[0][0], afr[0][1], afr[0][2], afr[0][3], aBase);
            ldsm_x4(afr[0][4], afr[0][5], afr[0][6], afr[0][7], aBase + 16 * 432);
            ldsm_x4(bfr[0][0], bfr[0][1], bfr[0][2], bfr[0][3], bBase);
            ldsm_x4(bfr[0][4], bfr[0][5], bfr[0][6], bfr[0][7], bBase + 16 * 432);
        }
#pragma unroll
        for (int ks = 0; ks < KSTEPS; ++ks) {
            const int cs = ks & 1, nx = cs ^ 1;
            if (ks + 1 < KSTEPS) {
                const uint32_t aA = aBase + (ks + 1) * 32;
                const uint32_t bA = bBase + (ks + 1) * 32;
                ldsm_x4(afr[nx][0], afr[nx][1], afr[nx][2], afr[nx][3], aA);
                ldsm_x4(afr[nx][4], afr[nx][5], afr[nx][6], afr[nx][7], aA + 16 * 432);
                ldsm_x4(bfr[nx][0], bfr[nx][1], bfr[nx][2], bfr[nx][3], bA);
                ldsm_x4(bfr[nx][4], bfr[nx][5], bfr[nx][6], bfr[nx][7], bA + 16 * 432);
            }
#pragma unroll
            for (int nt = 0; nt < 4; ++nt) {
                const uint32_t* bp = &bfr[cs][(nt >> 1) * 4 + (nt & 1) * 2];
                mma16816(dacc[0][nt], &afr[cs][0], bp);
                mma16816(dacc[1][nt], &afr[cs][4], bp);
            }
        }

        // ---- fold into per-point running max/max2 ----
#pragma unroll
        for (int mt = 0; mt < 2; ++mt)
#pragma unroll
            for (int nt = 0; nt < 4; ++nt) {
                int k0 = cb + wn * 32 + nt * 8 + 2 * (lane & 3);
#pragma unroll
                for (int c = 0; c < 4; ++c) {
                    int s = mt * 2 + (c >> 1);
                    float v = dacc[mt][nt][c];
                    int   k = k0 + (c & 1);
                    if (v > bestv[s]) { best2v[s] = bestv[s]; bestv[s] = v; bidx[s] = k; }
                    else if (v > best2v[s]) best2v[s] = v;
                }
            }

        if (ch + 1 < NCHUNK) {
            CP_WAIT0();
            __syncthreads();               // next B buffer resident & safe
        }
    }

    // ---- warp merge across the 4 lanes sharing each point ----
#pragma unroll
    for (int st = 1; st <= 2; st <<= 1) {
#pragma unroll
        for (int s = 0; s < 4; ++s) {
            float ob  = __shfl_xor_sync(0xFFFFFFFFu, bestv[s],  st);
            float ob2 = __shfl_xor_sync(0xFFFFFFFFu, best2v[s], st);
            int   oi  = __shfl_xor_sync(0xFFFFFFFFu, bidx[s],   st);
            if (ob > bestv[s]) {
                best2v[s] = fmaxf(bestv[s], ob2);
                bestv[s] = ob; bidx[s] = oi;
            } else {
                best2v[s] = fmaxf(best2v[s], ob);
            }
        }
    }
    if ((lane & 3) == 0) {
#pragma unroll
        for (int s = 0; s < 4; ++s) {
            int pt = wm * 32 + (lane >> 2) + s * 8;
            s_bm[wn * 128 + pt]  = bestv[s];
            s_b2m[wn * 128 + pt] = best2v[s];
            s_im[wn * 128 + pt]  = bidx[s];
        }
    }
    __syncthreads();

    // ---- final merge across the 4 warp columns, flag near-ties ----
    if (tid < MPTS) {
        float mx = -3.4e38f, m2 = -3.4e38f;
        int ix = 0;
#pragma unroll
        for (int c = 0; c < 4; ++c) {       // ascending c == ascending code idx
            float cb  = s_bm[c * 128 + tid];
            float cb2 = s_b2m[c * 128 + tid];
            int   ci  = s_im[c * 128 + tid];
            if (cb > mx) { m2 = fmaxf(mx, cb2); mx = cb; ix = ci; }
            else m2 = fmaxf(m2, fmaxf(cb2, cb));
        }
        s_fidx[tid] = ix;
        s_flag[tid] = (mx - m2 < MARGIN_D) ? 1 : 0;
    }
    __syncthreads();

    // ---- exact fp64 rescue for near-ties (block-parallel, rare) ----
    const float4* emb4 = reinterpret_cast<const float4*>(emb);
#pragma unroll 1
    for (int pt = 0; pt < MPTS; ++pt) {
        if (!s_flag[pt]) continue;        // uniform
        double bb = 1e300;
        int bi2 = 0;
#pragma unroll 1
        for (int q = 0; q < 2; ++q) {
            int k = tid * 2 + q;
            const float4* row = emb4 + (size_t)k * (Dm / 4);
            double ssum = 0.0;
#pragma unroll
            for (int jj = 0; jj < Dm / 4; ++jj) {
                float4 e = row[jj];
                double d0 = (double)z32[pt * 65 + 4 * jj]     - e.x;
                double d1 = (double)z32[pt * 65 + 4 * jj + 1] - e.y;
                double d2 = (double)z32[pt * 65 + 4 * jj + 2] - e.z;
                double d3 = (double)z32[pt * 65 + 4 * jj + 3] - e.w;
                ssum += d0 * d0 + d1 * d1 + d2 * d2 + d3 * d3;
            }
            if (ssum < bb) { bb = ssum; bi2 = k; }
        }
        s_rb[tid] = bb; s_ri[tid] = bi2;
        __syncthreads();
        for (int st = 256; st > 0; st >>= 1) {
            if (tid < st) {
                double o = s_rb[tid + st]; int oi = s_ri[tid + st];
                double m0 = s_rb[tid];     int mi = s_ri[tid];
                if (o < m0 || (o == m0 && oi < mi)) { s_rb[tid] = o; s_ri[tid] = oi; }
            }
            __syncthreads();
        }
        if (tid == 0) s_fidx[pt] = s_ri[0];
        __syncthreads();
    }
    __syncthreads();

    // ---- per-point outputs + EMA segment sums ----
    if (tid < MPTS) {
        int pt = tid, n = n0 + pt, idx = s_fidx[pt];
        g_indices[n] = idx;
        if (idx_out) idx_out[n] = (float)idx;
        atomicAdd(&g_counts[idx], 1.0f);
        float* dst = g_embed_sum + (size_t)idx * Dm;
#pragma unroll
        for (int j = 0; j < Dm / 4; ++j)
            red_add_v4(dst + 4 * j,
                       z32[pt * 65 + 4 * j],     z32[pt * 65 + 4 * j + 1],
                       z32[pt * 65 + 4 * j + 2], z32[pt * 65 + 4 * j + 3]);
    }
}

// ----------------- k_cluster ------------------------------------------------
__global__ void k_cluster(const float* __restrict__ cluster_size) {
    __shared__ float red[Km];
    int k = threadIdx.x;
    float ncs = fmaf(cluster_size[k], DECAY, (1.0f - DECAY) * g_counts[k]);
    red[k] = ncs;
    __syncthreads();
    for (int s = Km / 2; s > 0; s >>= 1) {
        if (k < s) red[k] += red[k + s];
        __syncthreads();
    }
    float n = red[0];
    g_smoothed[k] = __fmul_rn(__fdiv_rn(ncs + EPSm, n + (float)Km * EPSm), n);
}

// ----------------- k_embed --------------------------------------------------
__global__ void k_embed(const float* __restrict__ embed_avg) {
    int i = blockIdx.x * blockDim.x + threadIdx.x;
    float na = fmaf(embed_avg[i], DECAY, (1.0f - DECAY) * g_embed_sum[i]);
    g_new_embedding[i] = __fdiv_rn(na, g_smoothed[i >> 6]);
}

// ----------------- k_quant --------------------------------------------------
__global__ void __launch_bounds__(256)
k_quant(const float* __restrict__ z, float* __restrict__ out) {
    __shared__ float red[256];
    const int n = blockIdx.x * 256 + threadIdx.x;
    const int b = n >> 12;
    const int t = n & (Tm - 1);
    const float* zb = z + ((size_t)b * Dm) * Tm + t;
    float* ob = out + OFF_ZQ + ((size_t)b * Dm) * Tm + t;

    const int idx = g_indices[n];
    const float4* row = reinterpret_cast<const float4*>(g_new_embedding + (size_t)idx * Dm);

    float acc = 0.0f;
#pragma unroll
    for (int j = 0; j < Dm / 4; j++) {
        float4 e = row[j];
        float zv, df;
        zv = zb[(size_t)(4 * j + 0) * Tm]; ob[(size_t)(4 * j + 0) * Tm] = e.x; df = zv - e.x; acc = fmaf(df, df, acc);
        zv = zb[(size_t)(4 * j + 1) * Tm]; ob[(size_t)(4 * j + 1) * Tm] = e.y; df = zv - e.y; acc = fmaf(df, df, acc);
        zv = zb[(size_t)(4 * j + 2) * Tm]; ob[(size_t)(4 * j + 2) * Tm] = e.z; df = zv - e.z; acc = fmaf(df, df, acc);
        zv = zb[(size_t)(4 * j + 3) * Tm]; ob[(size_t)(4 * j + 3) * Tm] = e.w; df = zv - e.w; acc = fmaf(df, df, acc);
    }

    red[threadIdx.x] = acc;
    __syncthreads();
    for (int st = 128; st > 0; st >>= 1) {
        if (threadIdx.x < st) red[threadIdx.x] += red[threadIdx.x + st];
        __syncthreads();
    }
    if (threadIdx.x == 0) atomicAdd(&g_loss, red[0]);
}

// ----------------- k_final --------------------------------------------------
__global__ void k_final(float* __restrict__ loss_out) {
    loss_out[0] = 0.25f * __fdiv_rn(g_loss, (float)((size_t)Nm * Dm));
}

// ----------------- launch ----------------------------------------------------
extern "C" void kernel_launch(void* const* d_in, const int* in_sizes, int n_in,
                              void* d_out, int out_size) {
    const float* z    = (const float*)d_in[0];
    const float* emb  = (const float*)d_in[1];
    const float* cs   = (const float*)d_in[2];
    const float* avg  = (const float*)d_in[3];
    float* out = (float*)d_out;

    const bool full = ((size_t)out_size >= SZ_FULL);
    float* idx_out  = full ? out + OFF_IDX  : nullptr;
    float* loss_out = full ? out + OFF_LOSS : nullptr;

    cudaFuncSetAttribute(k_argmin, cudaFuncAttributeMaxDynamicSharedMemorySize, SMEM_SZ);

    k_zero1<<<Km * Dm / 2 / 1024, 1024>>>();
    k_zero2<<<(Km * Dm / 2 + Km + 1 + 1023) / 1024, 1024>>>();
    k_prep<<<Km / 256, 256>>>(emb);
    k_argmin<<<Nm / MPTS, NT, SMEM_SZ>>>(z, emb, idx_out);
    k_cluster<<<1, Km>>>(cs);
    k_embed<<<(Km * Dm) / 1024, 1024>>>(avg);
    k_quant<<<Nm / 256, 256>>>(z, out);
    if (loss_out) k_final<<<1, 1>>>(loss_out);
}